// round 10
// baseline (speedup 1.0000x reference)
#include <cuda_runtime.h>
#include <math.h>
#include <stdint.h>

// Shapes (fixed by the problem)
#define B_SZ   16
#define T_SEQ  1024
#define C_DIM  768
#define NH     12
#define DH     64
#define C3     2304       // 3*C
#define M_ROWS 16384      // B*T

// Scratch buffers (no cudaMalloc allowed)
__device__ float g_qkv[(size_t)M_ROWS * C3];   // [B*T, 3C]
__device__ float g_y[(size_t)M_ROWS * C_DIM];  // [B*T, C]

// ---------------------------------------------------------------------------
// Shared helpers
// ---------------------------------------------------------------------------
__device__ __forceinline__ uint32_t f2tf32(float x) {
    uint32_t y;
    asm volatile("cvt.rna.tf32.f32 %0, %1;" : "=r"(y) : "f"(x));
    return y;
}
__device__ __forceinline__ uint4 cvt4(float4 v) {
    return make_uint4(f2tf32(v.x), f2tf32(v.y), f2tf32(v.z), f2tf32(v.w));
}
__device__ __forceinline__ uint4 cvt4s(float4 v, float s) {
    return make_uint4(f2tf32(v.x * s), f2tf32(v.y * s), f2tf32(v.z * s), f2tf32(v.w * s));
}

__device__ __forceinline__ void mma_tf32(float* c, const uint32_t* a, const uint32_t* b) {
    asm volatile(
        "mma.sync.aligned.m16n8k8.row.col.f32.tf32.tf32.f32 "
        "{%0,%1,%2,%3}, {%4,%5,%6,%7}, {%8,%9}, {%0,%1,%2,%3};"
        : "+f"(c[0]), "+f"(c[1]), "+f"(c[2]), "+f"(c[3])
        : "r"(a[0]), "r"(a[1]), "r"(a[2]), "r"(a[3]), "r"(b[0]), "r"(b[1]));
}

// ---------------------------------------------------------------------------
// TF32 GEMM v4: C = A[M,K] @ B[K,N] + bias[N], row-major.
// CTA 256x128, 8 warps (4x2), warp tile 64x64, BK=32.
// 2-stage smem double buffer: ONE __syncthreads per k-iter; STS of tile c+1
// and LDG of tile c+2 overlap compute of tile c.
// ---------------------------------------------------------------------------
#define GBM 256
#define GBN 128
#define GBK 32
#define GAP 36    // As pitch (words)
#define GBP 136   // Bs pitch (words)
#define GSTAGE (GBM * GAP + GBK * GBP)            // 13568 words per stage
#define GEMM_SMEM (2 * GSTAGE * 4)                // 108544 B

__global__ __launch_bounds__(256, 1) void tf32_gemm_bias(
    const float* __restrict__ A, const float* __restrict__ B,
    const float* __restrict__ bias, float* __restrict__ C,
    int M, int N, int K)
{
    extern __shared__ uint32_t gsm[];

    const int tid  = threadIdx.x;
    const int wid  = tid >> 5;
    const int lane = tid & 31;
    const int wm   = wid >> 1;      // 0..3
    const int wn   = wid & 1;       // 0..1
    const int g    = lane >> 2;     // 0..7
    const int tg   = lane & 3;      // 0..3

    const int ar = tid >> 3;            // 0..31
    const int ac = (tid & 7) * 4;       // 0..28
    const int bkr = tid >> 3;           // 0..31
    const int bc  = (tid & 7) * 4;      // 0..28

    const float* Ag = A + (size_t)(blockIdx.y * GBM + ar) * K + ac;
    const float* Bg = B + (size_t)bkr * N + blockIdx.x * GBN + bc;

    float acc[4][8][4];
#pragma unroll
    for (int mt = 0; mt < 4; mt++)
#pragma unroll
        for (int nt = 0; nt < 8; nt++)
#pragma unroll
            for (int c = 0; c < 4; c++) acc[mt][nt][c] = 0.f;

    const int NCH = K / GBK;
    float4 pa[8], pb[4];

    // ---- prologue: tile0 -> stage0, prefetch tile1 to regs ----
#pragma unroll
    for (int i = 0; i < 8; i++) pa[i] = *(const float4*)(Ag + (size_t)(32 * i) * K);
#pragma unroll
    for (int j = 0; j < 4; j++) pb[j] = *(const float4*)(Bg + 32 * j);
    {
        uint32_t* As0 = gsm;
        uint32_t* Bs0 = gsm + GBM * GAP;
#pragma unroll
        for (int i = 0; i < 8; i++) *(uint4*)&As0[(ar + 32 * i) * GAP + ac] = cvt4(pa[i]);
#pragma unroll
        for (int j = 0; j < 4; j++) *(uint4*)&Bs0[bkr * GBP + bc + 32 * j] = cvt4(pb[j]);
    }
    if (NCH > 1) {
#pragma unroll
        for (int i = 0; i < 8; i++)
            pa[i] = *(const float4*)(Ag + (size_t)(32 * i) * K + GBK);
#pragma unroll
        for (int j = 0; j < 4; j++)
            pb[j] = *(const float4*)(Bg + (size_t)GBK * N + 32 * j);
    }
    __syncthreads();

    for (int c = 0; c < NCH; c++) {
        const int s = c & 1;
        uint32_t* Asr = gsm + s * GSTAGE;
        uint32_t* Bsr = Asr + GBM * GAP;
        uint32_t* Asw = gsm + (s ^ 1) * GSTAGE;
        uint32_t* Bsw = Asw + GBM * GAP;

        // store tile c+1 (in regs) into the free stage
        if (c + 1 < NCH) {
#pragma unroll
            for (int i = 0; i < 8; i++) *(uint4*)&Asw[(ar + 32 * i) * GAP + ac] = cvt4(pa[i]);
#pragma unroll
            for (int j = 0; j < 4; j++) *(uint4*)&Bsw[bkr * GBP + bc + 32 * j] = cvt4(pb[j]);
        }
        // issue loads for tile c+2
        if (c + 2 < NCH) {
            const int kofs = (c + 2) * GBK;
#pragma unroll
            for (int i = 0; i < 8; i++)
                pa[i] = *(const float4*)(Ag + (size_t)(32 * i) * K + kofs);
#pragma unroll
            for (int j = 0; j < 4; j++)
                pb[j] = *(const float4*)(Bg + (size_t)kofs * N + 32 * j);
        }

        // compute tile c
#pragma unroll
        for (int ks = 0; ks < 4; ks++) {
            const int kk = ks * 8 + tg;
            uint32_t af[4][4], bf[8][2];
#pragma unroll
            for (int mt = 0; mt < 4; mt++) {
                const int am = wm * 64 + mt * 16;
                af[mt][0] = Asr[(am + g    ) * GAP + kk    ];
                af[mt][1] = Asr[(am + g + 8) * GAP + kk    ];
                af[mt][2] = Asr[(am + g    ) * GAP + kk + 4];
                af[mt][3] = Asr[(am + g + 8) * GAP + kk + 4];
            }
#pragma unroll
            for (int nt = 0; nt < 8; nt++) {
                const int bn = wn * 64 + nt * 8 + g;
                bf[nt][0] = Bsr[(kk    ) * GBP + bn];
                bf[nt][1] = Bsr[(kk + 4) * GBP + bn];
            }
#pragma unroll
            for (int mt = 0; mt < 4; mt++)
#pragma unroll
                for (int nt = 0; nt < 8; nt++)
                    mma_tf32(acc[mt][nt], af[mt], bf[nt]);
        }
        __syncthreads();
    }

    const int crow0 = blockIdx.y * GBM + wm * 64;
    const int ccol0 = blockIdx.x * GBN + wn * 64;
#pragma unroll
    for (int mt = 0; mt < 4; mt++) {
#pragma unroll
        for (int nt = 0; nt < 8; nt++) {
            const int row = crow0 + mt * 16 + g;
            const int col = ccol0 + nt * 8 + 2 * tg;
            const float b0 = bias[col], b1 = bias[col + 1];
            float2 v0 = make_float2(acc[mt][nt][0] + b0, acc[mt][nt][1] + b1);
            float2 v1 = make_float2(acc[mt][nt][2] + b0, acc[mt][nt][3] + b1);
            *(float2*)(C + (size_t)row * N + col)       = v0;
            *(float2*)(C + (size_t)(row + 8) * N + col) = v1;
        }
    }
}

// ---------------------------------------------------------------------------
// Flash-attention v3 on mma.sync TF32 with K/V LDG prefetch.
// q-tile 128, 4 warps; warp w owns rows 32w..32w+31 (mt=2).
// K/V for tile i+1 are loaded to registers during tile i's compute.
// ---------------------------------------------------------------------------
#define AP 68
#define ATTN_SMEM ((128 + 64 + 64 + 128) * AP * 4)   // 104448 B

__global__ __launch_bounds__(128, 2) void attn_mma_kernel(
    const float* __restrict__ qkv, float* __restrict__ y)
{
    extern __shared__ uint32_t smu[];
    uint32_t* Qs = smu;                   // [128][AP]
    uint32_t* Ks = smu + 128 * AP;        // [64][AP]
    uint32_t* Vs = smu + 192 * AP;        // [64][AP]
    uint32_t* Ps = smu + 256 * AP;        // [128][AP]

    const int q0 = blockIdx.x * 128;
    const int h  = blockIdx.y;
    const int b  = blockIdx.z;

    const int tid  = threadIdx.x;
    const int w    = tid >> 5;
    const int lane = tid & 31;
    const int g    = lane >> 2;
    const int tg   = lane & 3;

    const int lr   = tid >> 1;            // 0..63
    const int colb = (tid & 1) * 16;      // 0 or 16

    // ---- prefetch K/V tile 0 into registers ----
    float4 kreg[8], vreg[8];
    {
        const float* kb = qkv + ((size_t)(b * T_SEQ + lr)) * C3 + C_DIM + h * DH;
        const float* vb = qkv + ((size_t)(b * T_SEQ + lr)) * C3 + 2 * C_DIM + h * DH;
#pragma unroll
        for (int hs = 0; hs < 2; hs++) {
            const int c0 = colb + 32 * hs;
#pragma unroll
            for (int j = 0; j < 4; j++) {
                kreg[hs * 4 + j] = *(const float4*)(kb + c0 + 4 * j);
                vreg[hs * 4 + j] = *(const float4*)(vb + c0 + 4 * j);
            }
        }
    }

    // ---- load Q tile (128 rows, scaled, tf32) ----
#pragma unroll
    for (int rh = 0; rh < 2; rh++) {
        const int rr = lr + 64 * rh;
        const float* src = qkv + ((size_t)(b * T_SEQ + q0 + rr)) * C3 + h * DH;
        uint32_t* dst = Qs + rr * AP;
#pragma unroll
        for (int hs = 0; hs < 2; hs++) {
            const int c0 = colb + 32 * hs;
#pragma unroll
            for (int j = 0; j < 4; j++)
                *(uint4*)(dst + c0 + 4 * j) = cvt4s(*(const float4*)(src + c0 + 4 * j), 0.125f);
        }
    }

    float m[2][2], l[2][2], o[2][8][4];
#pragma unroll
    for (int mt = 0; mt < 2; mt++) {
        m[mt][0] = -1e30f; m[mt][1] = -1e30f;
        l[mt][0] = 0.f;    l[mt][1] = 0.f;
#pragma unroll
        for (int nt = 0; nt < 8; nt++)
#pragma unroll
            for (int c = 0; c < 4; c++) o[mt][nt][c] = 0.f;
    }

    const int rowg0 = 32 * w + g;
    const int kmax  = q0 + 64;

    for (int k0 = 0; k0 <= kmax; k0 += 64) {
        __syncthreads();   // prev compute done with Ks/Vs (and Q STS visible on iter 0)

        // ---- store prefetched K/V (cvt to tf32) ----
        {
            uint32_t* kd = Ks + lr * AP;
            uint32_t* vd = Vs + lr * AP;
#pragma unroll
            for (int hs = 0; hs < 2; hs++) {
                const int c0 = colb + 32 * hs;
#pragma unroll
                for (int j = 0; j < 4; j++) {
                    *(uint4*)(kd + c0 + 4 * j) = cvt4(kreg[hs * 4 + j]);
                    *(uint4*)(vd + c0 + 4 * j) = cvt4(vreg[hs * 4 + j]);
                }
            }
        }
        __syncthreads();

        // ---- issue LDG for next K/V tile (covered by this iter's compute) ----
        if (k0 + 64 <= kmax) {
            const float* kb = qkv + ((size_t)(b * T_SEQ + k0 + 64 + lr)) * C3 + C_DIM + h * DH;
            const float* vb = qkv + ((size_t)(b * T_SEQ + k0 + 64 + lr)) * C3 + 2 * C_DIM + h * DH;
#pragma unroll
            for (int hs = 0; hs < 2; hs++) {
                const int c0 = colb + 32 * hs;
#pragma unroll
                for (int j = 0; j < 4; j++) {
                    kreg[hs * 4 + j] = *(const float4*)(kb + c0 + 4 * j);
                    vreg[hs * 4 + j] = *(const float4*)(vb + c0 + 4 * j);
                }
            }
        }

        // ---- S = Q @ K^T ----
        float s[2][8][4];
#pragma unroll
        for (int mt = 0; mt < 2; mt++)
#pragma unroll
            for (int nt = 0; nt < 8; nt++)
#pragma unroll
                for (int c = 0; c < 4; c++) s[mt][nt][c] = 0.f;

#pragma unroll
        for (int ks = 0; ks < 8; ks++) {
            const int kk = ks * 8 + tg;
            uint32_t af[2][4];
#pragma unroll
            for (int mt = 0; mt < 2; mt++) {
                const int r = rowg0 + 16 * mt;
                af[mt][0] = Qs[(r    ) * AP + kk    ];
                af[mt][1] = Qs[(r + 8) * AP + kk    ];
                af[mt][2] = Qs[(r    ) * AP + kk + 4];
                af[mt][3] = Qs[(r + 8) * AP + kk + 4];
            }
#pragma unroll
            for (int nt = 0; nt < 8; nt++) {
                uint32_t bb[2];
                bb[0] = Ks[(nt * 8 + g) * AP + kk    ];
                bb[1] = Ks[(nt * 8 + g) * AP + kk + 4];
                mma_tf32(s[0][nt], af[0], bb);
                mma_tf32(s[1][nt], af[1], bb);
            }
        }

        // ---- causal mask ----
        if (k0 >= q0) {
            const int dk = k0 - q0;
#pragma unroll
            for (int mt = 0; mt < 2; mt++) {
                const int r0 = rowg0 + 16 * mt;
#pragma unroll
                for (int nt = 0; nt < 8; nt++) {
                    const int c0 = nt * 8 + 2 * tg + dk;
                    if (c0     > r0    ) s[mt][nt][0] = -1e30f;
                    if (c0 + 1 > r0    ) s[mt][nt][1] = -1e30f;
                    if (c0     > r0 + 8) s[mt][nt][2] = -1e30f;
                    if (c0 + 1 > r0 + 8) s[mt][nt][3] = -1e30f;
                }
            }
        }

        // ---- online softmax ----
#pragma unroll
        for (int mt = 0; mt < 2; mt++) {
            float mx0 = -1e30f, mx1 = -1e30f;
#pragma unroll
            for (int nt = 0; nt < 8; nt++) {
                mx0 = fmaxf(mx0, fmaxf(s[mt][nt][0], s[mt][nt][1]));
                mx1 = fmaxf(mx1, fmaxf(s[mt][nt][2], s[mt][nt][3]));
            }
            mx0 = fmaxf(mx0, __shfl_xor_sync(0xffffffffu, mx0, 1));
            mx0 = fmaxf(mx0, __shfl_xor_sync(0xffffffffu, mx0, 2));
            mx1 = fmaxf(mx1, __shfl_xor_sync(0xffffffffu, mx1, 1));
            mx1 = fmaxf(mx1, __shfl_xor_sync(0xffffffffu, mx1, 2));

            const float mn0 = fmaxf(m[mt][0], mx0);
            const float mn1 = fmaxf(m[mt][1], mx1);
            const float f0  = __expf(m[mt][0] - mn0);
            const float f1  = __expf(m[mt][1] - mn1);

            const int r0 = rowg0 + 16 * mt;
            float sum0 = 0.f, sum1 = 0.f;
#pragma unroll
            for (int nt = 0; nt < 8; nt++) {
                float p0 = __expf(s[mt][nt][0] - mn0);
                float p1 = __expf(s[mt][nt][1] - mn0);
                float p2 = __expf(s[mt][nt][2] - mn1);
                float p3 = __expf(s[mt][nt][3] - mn1);
                sum0 += p0 + p1;
                sum1 += p2 + p3;
                uint32_t* p0d = Ps + (r0    ) * AP + nt * 8 + 2 * tg;
                uint32_t* p1d = Ps + (r0 + 8) * AP + nt * 8 + 2 * tg;
                p0d[0] = f2tf32(p0); p0d[1] = f2tf32(p1);
                p1d[0] = f2tf32(p2); p1d[1] = f2tf32(p3);
            }
            sum0 += __shfl_xor_sync(0xffffffffu, sum0, 1);
            sum0 += __shfl_xor_sync(0xffffffffu, sum0, 2);
            sum1 += __shfl_xor_sync(0xffffffffu, sum1, 1);
            sum1 += __shfl_xor_sync(0xffffffffu, sum1, 2);

            l[mt][0] = l[mt][0] * f0 + sum0;  m[mt][0] = mn0;
            l[mt][1] = l[mt][1] * f1 + sum1;  m[mt][1] = mn1;
#pragma unroll
            for (int nt = 0; nt < 8; nt++) {
                o[mt][nt][0] *= f0; o[mt][nt][1] *= f0;
                o[mt][nt][2] *= f1; o[mt][nt][3] *= f1;
            }
        }
        __syncwarp();

        // ---- O += P @ V ----
#pragma unroll
        for (int ks = 0; ks < 8; ks++) {
            const int kk = ks * 8 + tg;
            uint32_t af[2][4];
#pragma unroll
            for (int mt = 0; mt < 2; mt++) {
                const int r = rowg0 + 16 * mt;
                af[mt][0] = Ps[(r    ) * AP + kk    ];
                af[mt][1] = Ps[(r + 8) * AP + kk    ];
                af[mt][2] = Ps[(r    ) * AP + kk + 4];
                af[mt][3] = Ps[(r + 8) * AP + kk + 4];
            }
#pragma unroll
            for (int nt = 0; nt < 8; nt++) {
                uint32_t bb[2];
                bb[0] = Vs[(kk    ) * AP + nt * 8 + g];
                bb[1] = Vs[(kk + 4) * AP + nt * 8 + g];
                mma_tf32(o[0][nt], af[0], bb);
                mma_tf32(o[1][nt], af[1], bb);
            }
        }
    }

    // ---- normalize, stage to smem, coalesced write ----
    __syncthreads();
    float* Of = (float*)Ps;
#pragma unroll
    for (int mt = 0; mt < 2; mt++) {
        const int r0 = rowg0 + 16 * mt;
        const float inv0 = 1.f / l[mt][0];
        const float inv1 = 1.f / l[mt][1];
#pragma unroll
        for (int nt = 0; nt < 8; nt++) {
            float* d0 = Of + (r0    ) * AP + nt * 8 + 2 * tg;
            float* d1 = Of + (r0 + 8) * AP + nt * 8 + 2 * tg;
            d0[0] = o[mt][nt][0] * inv0; d0[1] = o[mt][nt][1] * inv0;
            d1[0] = o[mt][nt][2] * inv1; d1[1] = o[mt][nt][3] * inv1;
        }
    }
    __syncthreads();
#pragma unroll
    for (int rh = 0; rh < 2; rh++) {
        const int rr = lr + 64 * rh;
        const float* src = Of + rr * AP;
        float* dst = y + ((size_t)(b * T_SEQ + q0 + rr)) * C_DIM + h * DH;
#pragma unroll
        for (int hs = 0; hs < 2; hs++) {
            const int c0 = colb + 32 * hs;
#pragma unroll
            for (int j = 0; j < 4; j++)
                *(float4*)(dst + c0 + 4 * j) = *(const float4*)(src + c0 + 4 * j);
        }
    }
}

// ---------------------------------------------------------------------------
extern "C" void kernel_launch(void* const* d_in, const int* in_sizes, int n_in,
                              void* d_out, int out_size)
{
    const float* x     = (const float*)d_in[0];
    const float* Wqkv  = (const float*)d_in[1];
    const float* bqkv  = (const float*)d_in[2];
    const float* Wproj = (const float*)d_in[3];
    const float* bproj = (const float*)d_in[4];
    float* out = (float*)d_out;

    float *qkv, *y;
    cudaGetSymbolAddress((void**)&qkv, g_qkv);
    cudaGetSymbolAddress((void**)&y, g_y);

    cudaFuncSetAttribute(tf32_gemm_bias,
                         cudaFuncAttributeMaxDynamicSharedMemorySize, GEMM_SMEM);
    cudaFuncSetAttribute(attn_mma_kernel,
                         cudaFuncAttributeMaxDynamicSharedMemorySize, ATTN_SMEM);

    // 1) QKV projection (tensor cores, TF32)
    tf32_gemm_bias<<<dim3(C3 / GBN, M_ROWS / GBM), 256, GEMM_SMEM>>>(
        x, Wqkv, bqkv, qkv, M_ROWS, C3, C_DIM);

    // 2) causal attention (tensor cores, TF32)
    attn_mma_kernel<<<dim3(T_SEQ / 128, NH, B_SZ), 128, ATTN_SMEM>>>(qkv, y);

    // 3) output projection (tensor cores, TF32)
    tf32_gemm_bias<<<dim3(C_DIM / GBN, M_ROWS / GBM), 256, GEMM_SMEM>>>(
        y, Wproj, bproj, out, M_ROWS, C_DIM, C_DIM);
}